// round 1
// baseline (speedup 1.0000x reference)
#include <cuda_runtime.h>

#define S_SPANS 4096
#define K_ANT   64
#define N_MENT  4096
#define G_DIM   512
#define H_DIM   150
#define HPAD    160
#define KC      32
#define AB_ROWS 16

// ---------------- scratch (device globals; no allocation) ----------------
__device__ float g_A[N_MENT * H_DIM];   // g_i @ W1[0:512]
__device__ float g_B[N_MENT * H_DIM];   // g_i @ W1[512:1024]
__device__ float g_Ed[10 * H_DIM];      // dist_embed @ W1[1536:1556] + b1
__device__ float g_Eg[7 * H_DIM];       // genre_embed @ W1[1556:1576]
__device__ float g_Es[3 * H_DIM];       // speaker_embed @ W1[1576:1596]

// ---------------- tiny tables: phi-term factored per embedding ----------------
__global__ void tables_kernel(const float* __restrict__ dist_embed,
                              const float* __restrict__ genre_embed,
                              const float* __restrict__ speaker_embed,
                              const float* __restrict__ W1,
                              const float* __restrict__ b1) {
    int idx = blockIdx.x * blockDim.x + threadIdx.x;
    if (idx < 10 * H_DIM) {
        int d = idx / H_DIM, j = idx % H_DIM;
        float acc = b1[j];
        #pragma unroll
        for (int t = 0; t < 20; t++)
            acc += dist_embed[d * 20 + t] * W1[(1536 + t) * H_DIM + j];
        g_Ed[idx] = acc;
    } else if (idx < 17 * H_DIM) {
        int r = idx - 10 * H_DIM;
        int d = r / H_DIM, j = r % H_DIM;
        float acc = 0.f;
        #pragma unroll
        for (int t = 0; t < 20; t++)
            acc += genre_embed[d * 20 + t] * W1[(1556 + t) * H_DIM + j];
        g_Eg[r] = acc;
    } else if (idx < 20 * H_DIM) {
        int r = idx - 17 * H_DIM;
        int d = r / H_DIM, j = r % H_DIM;
        float acc = 0.f;
        #pragma unroll
        for (int t = 0; t < 20; t++)
            acc += speaker_embed[d * 20 + t] * W1[(1576 + t) * H_DIM + j];
        g_Es[r] = acc;
    }
}

// ---------------- A/B precompute: [4096,512] @ [512,150] x2 ----------------
__global__ __launch_bounds__(160) void ab_kernel(const float* __restrict__ g_i,
                                                 const float* __restrict__ W1) {
    __shared__ float sg[AB_ROWS][G_DIM];
    int n0 = blockIdx.x * AB_ROWS;
    for (int idx = threadIdx.x; idx < AB_ROWS * G_DIM; idx += blockDim.x) {
        int r = idx / G_DIM, k = idx % G_DIM;
        sg[r][k] = g_i[(n0 + r) * G_DIM + k];
    }
    __syncthreads();
    int j = threadIdx.x;
    if (j < H_DIM) {
        float accA[AB_ROWS], accB[AB_ROWS];
        #pragma unroll
        for (int r = 0; r < AB_ROWS; r++) { accA[r] = 0.f; accB[r] = 0.f; }
        for (int k = 0; k < G_DIM; k++) {
            float wa = W1[k * H_DIM + j];
            float wb = W1[(G_DIM + k) * H_DIM + j];
            #pragma unroll
            for (int r = 0; r < AB_ROWS; r++) {
                float gv = sg[r][k];
                accA[r] += gv * wa;
                accB[r] += gv * wb;
            }
        }
        #pragma unroll
        for (int r = 0; r < AB_ROWS; r++) {
            g_A[(n0 + r) * H_DIM + j] = accA[r];
            g_B[(n0 + r) * H_DIM + j] = accB[r];
        }
    }
}

// ---------------- main: product-GEMM + epilogue + fused per-span softmax ----------------
// block = one span (64 pairs). 256 threads: tj = t&15 (col group of 10), tp = t>>4 (4 pairs).
__global__ __launch_bounds__(256, 3) void main_kernel(
    const float* __restrict__ g_i, const float* __restrict__ ms,
    const float* __restrict__ W1, const float* __restrict__ W2,
    const float* __restrict__ b2,
    const int* __restrict__ mention_ids, const int* __restrict__ antecedent_ids,
    const int* __restrict__ distances, const int* __restrict__ genres,
    const int* __restrict__ speakers, const int* __restrict__ ant_counts,
    float* __restrict__ out)
{
    __shared__ int   sm_m[K_ANT], sm_a[K_ANT];
    __shared__ float sc[K_ANT][KC + 4];   // banks (4p + k) % 32 -> conflict-free
    __shared__ float sW[KC][HPAD];        // cols 150..159 zero
    __shared__ float sScore[K_ANT];

    int s = blockIdx.x;
    int t = threadIdx.x;
    if (t < K_ANT) {
        int gp = s * K_ANT + t;
        sm_m[t] = mention_ids[gp];
        sm_a[t] = antecedent_ids[gp];
    }
    int tj = t & 15;
    int tp = t >> 4;

    float acc[4][10];
    #pragma unroll
    for (int i = 0; i < 4; i++)
        #pragma unroll
        for (int jj = 0; jj < 10; jj++) acc[i][jj] = 0.f;

    for (int kb = 0; kb < G_DIM; kb += KC) {
        __syncthreads();
        // stage W1c chunk [KC x 160]
        for (int idx = t; idx < KC * HPAD; idx += 256) {
            int k = idx / HPAD, j = idx % HPAD;
            sW[k][j] = (j < H_DIM) ? W1[(1024 + kb + k) * H_DIM + j] : 0.f;
        }
        // stage product chunk: c[p][k] = g[m_p][kb+k] * g[a_p][kb+k]  (coalesced 128B)
        for (int idx = t; idx < K_ANT * KC; idx += 256) {
            int kk = idx & (KC - 1);
            int p  = idx >> 5;
            int col = kb + kk;
            sc[p][kk] = g_i[sm_m[p] * G_DIM + col] * g_i[sm_a[p] * G_DIM + col];
        }
        __syncthreads();
        #pragma unroll 4
        for (int k = 0; k < KC; k++) {
            float cv[4], wv[10];
            #pragma unroll
            for (int i = 0; i < 4; i++) cv[i] = sc[tp * 4 + i][k];
            #pragma unroll
            for (int jj = 0; jj < 10; jj++) wv[jj] = sW[k][tj * 10 + jj];
            #pragma unroll
            for (int i = 0; i < 4; i++)
                #pragma unroll
                for (int jj = 0; jj < 10; jj++)
                    acc[i][jj] += cv[i] * wv[jj];
        }
    }

    // epilogue: pre-terms + ReLU + dot with W2 (tj==15 owns only padding cols)
    float partial[4] = {0.f, 0.f, 0.f, 0.f};
    if (tj < 15) {
        #pragma unroll
        for (int i = 0; i < 4; i++) {
            int p  = tp * 4 + i;
            int gp = s * K_ANT + p;
            int m = sm_m[p], a = sm_a[p];
            int d = distances[gp];
            int bucket = (d >= 1) + (d >= 2) + (d >= 3) + (d >= 4) +
                         (d >= 8) + (d >= 16) + (d >= 32) + (d >= 64);
            const float* Ap  = g_A + m * H_DIM;
            const float* Bp  = g_B + a * H_DIM;
            const float* Edp = g_Ed + bucket * H_DIM;
            const float* Egp = g_Eg + genres[gp] * H_DIM;
            const float* Esp = g_Es + speakers[gp] * H_DIM;
            float ps = 0.f;
            #pragma unroll
            for (int jj = 0; jj < 10; jj++) {
                int j = tj * 10 + jj;
                float h = acc[i][jj] + Ap[j] + Bp[j] + Edp[j] + Egp[j] + Esp[j];
                h = h > 0.f ? h : 0.f;
                ps += h * W2[j];
            }
            partial[i] = ps;
        }
    }
    // reduce the 16 tj groups (16-lane segments within each warp)
    #pragma unroll
    for (int off = 8; off >= 1; off >>= 1)
        #pragma unroll
        for (int i = 0; i < 4; i++)
            partial[i] += __shfl_xor_sync(0xffffffffu, partial[i], off, 16);
    if (tj == 0) {
        #pragma unroll
        for (int i = 0; i < 4; i++) {
            int p = tp * 4 + i;
            sScore[p] = partial[i] + b2[0] + ms[sm_m[p]] + ms[sm_a[p]];
        }
    }
    __syncthreads();

    // fused masked softmax over 64 antecedents + epsilon column, pad invalid with 1000
    if (t < 32) {
        int cnt = ant_counts[s];
        float v0 = sScore[t], v1 = sScore[t + 32];
        bool val0 = t < cnt, val1 = (t + 32) < cnt;
        float mx = 0.f;  // epsilon logit = 0
        if (val0) mx = fmaxf(mx, v0);
        if (val1) mx = fmaxf(mx, v1);
        #pragma unroll
        for (int off = 16; off >= 1; off >>= 1)
            mx = fmaxf(mx, __shfl_xor_sync(0xffffffffu, mx, off));
        float e0 = val0 ? expf(v0 - mx) : 0.f;
        float e1 = val1 ? expf(v1 - mx) : 0.f;
        float sum = e0 + e1;
        #pragma unroll
        for (int off = 16; off >= 1; off >>= 1)
            sum += __shfl_xor_sync(0xffffffffu, sum, off);
        float eps = expf(-mx);
        sum += eps;
        float inv = 1.0f / sum;
        float* orow = out + (size_t)s * (K_ANT + 1);
        orow[t]      = val0 ? e0 * inv : 1000.0f;
        orow[t + 32] = val1 ? e1 * inv : 1000.0f;
        if (t == 0) orow[K_ANT] = eps * inv;
    }
}

extern "C" void kernel_launch(void* const* d_in, const int* in_sizes, int n_in,
                              void* d_out, int out_size) {
    const float* g_i            = (const float*)d_in[0];
    const float* mention_scores = (const float*)d_in[1];
    const float* dist_embed     = (const float*)d_in[2];
    const float* genre_embed    = (const float*)d_in[3];
    const float* speaker_embed  = (const float*)d_in[4];
    const float* W1             = (const float*)d_in[5];
    const float* b1             = (const float*)d_in[6];
    const float* W2             = (const float*)d_in[7];
    const float* b2             = (const float*)d_in[8];
    const int*   mention_ids    = (const int*)d_in[9];
    const int*   antecedent_ids = (const int*)d_in[10];
    const int*   distances      = (const int*)d_in[11];
    const int*   genres         = (const int*)d_in[12];
    const int*   speakers       = (const int*)d_in[13];
    const int*   ant_counts     = (const int*)d_in[14];
    float* out = (float*)d_out;

    tables_kernel<<<(20 * H_DIM + 255) / 256, 256>>>(dist_embed, genre_embed,
                                                     speaker_embed, W1, b1);
    ab_kernel<<<N_MENT / AB_ROWS, 160>>>(g_i, W1);
    main_kernel<<<S_SPANS, 256>>>(g_i, mention_scores, W1, W2, b2,
                                  mention_ids, antecedent_ids, distances,
                                  genres, speakers, ant_counts, out);
}

// round 7
// speedup vs baseline: 1.2631x; 1.2631x over previous
#include <cuda_runtime.h>
#include <cstdint>

#define S_SPANS 4096
#define K_ANT   64
#define N_MENT  4096
#define G_DIM   512
#define H_DIM   150
#define NPAD    160
#define AB_ROWS 16

// sAdd row stride (floats)
#define ADDP 153
// sProd row stride (floats); 36*4=144B, 16B-aligned, A-frag bank = (4g+t) conflict-free
#define PRDP 36

// ---------------- scratch (device globals; no allocation) ----------------
__device__ float g_A[N_MENT * H_DIM];   // g_i @ W1[0:512]
__device__ float g_B[N_MENT * H_DIM];   // g_i @ W1[512:1024]
__device__ float g_Ed[10 * H_DIM];      // dist_embed @ W1[1536:1556] + b1
__device__ float g_Eg[7 * H_DIM];       // genre_embed @ W1[1556:1576]
__device__ float g_Es[3 * H_DIM];       // speaker_embed @ W1[1576:1596]

// ---------------- SMEM layout (bytes) ----------------
#define OFF_PROD 0                                  // 128*36*4   = 18432
#define OFF_WB   18432                              // 4*160*4*2*4= 20480
#define OFF_ADD  38912                              // 128*153*4  = 78336
#define OFF_W2   117248                             // 160*4
#define OFF_MS   117888                             // 128*4
#define OFF_M    118400                             // 128*4
#define OFF_AI   118912                             // 128*4
#define OFF_PART 119424                             // 128*4*4 = 2048
#define OFF_SC   121472                             // 128*4
#define SMEM_TOTAL 121984

__device__ __forceinline__ uint32_t f2tf32(float f) {
    uint32_t u;
    asm("cvt.rna.tf32.f32 %0, %1;" : "=r"(u) : "f"(f));
    return u;
}

__device__ __forceinline__ void mma_tf32(float* d, const uint32_t* a, const uint32_t* b) {
    asm volatile(
        "mma.sync.aligned.m16n8k8.row.col.f32.tf32.tf32.f32 "
        "{%0,%1,%2,%3}, {%4,%5,%6,%7}, {%8,%9}, {%0,%1,%2,%3};"
        : "+f"(d[0]), "+f"(d[1]), "+f"(d[2]), "+f"(d[3])
        : "r"(a[0]), "r"(a[1]), "r"(a[2]), "r"(a[3]), "r"(b[0]), "r"(b[1]));
}

// ---------------- tiny tables ----------------
__global__ void tables_kernel(const float* __restrict__ dist_embed,
                              const float* __restrict__ genre_embed,
                              const float* __restrict__ speaker_embed,
                              const float* __restrict__ W1,
                              const float* __restrict__ b1) {
    int idx = blockIdx.x * blockDim.x + threadIdx.x;
    if (idx < 10 * H_DIM) {
        int d = idx / H_DIM, j = idx % H_DIM;
        float acc = b1[j];
        #pragma unroll
        for (int t = 0; t < 20; t++)
            acc += dist_embed[d * 20 + t] * W1[(1536 + t) * H_DIM + j];
        g_Ed[idx] = acc;
    } else if (idx < 17 * H_DIM) {
        int r = idx - 10 * H_DIM;
        int d = r / H_DIM, j = r % H_DIM;
        float acc = 0.f;
        #pragma unroll
        for (int t = 0; t < 20; t++)
            acc += genre_embed[d * 20 + t] * W1[(1556 + t) * H_DIM + j];
        g_Eg[r] = acc;
    } else if (idx < 20 * H_DIM) {
        int r = idx - 17 * H_DIM;
        int d = r / H_DIM, j = r % H_DIM;
        float acc = 0.f;
        #pragma unroll
        for (int t = 0; t < 20; t++)
            acc += speaker_embed[d * 20 + t] * W1[(1576 + t) * H_DIM + j];
        g_Es[r] = acc;
    }
}

// ---------------- A/B precompute ----------------
__global__ __launch_bounds__(160) void ab_kernel(const float* __restrict__ g_i,
                                                 const float* __restrict__ W1) {
    __shared__ float sg[AB_ROWS][G_DIM];
    int n0 = blockIdx.x * AB_ROWS;
    for (int idx = threadIdx.x; idx < AB_ROWS * G_DIM; idx += blockDim.x) {
        int r = idx / G_DIM, k = idx % G_DIM;
        sg[r][k] = g_i[(n0 + r) * G_DIM + k];
    }
    __syncthreads();
    int j = threadIdx.x;
    if (j < H_DIM) {
        float accA[AB_ROWS], accB[AB_ROWS];
        #pragma unroll
        for (int r = 0; r < AB_ROWS; r++) { accA[r] = 0.f; accB[r] = 0.f; }
        for (int k = 0; k < G_DIM; k++) {
            float wa = W1[k * H_DIM + j];
            float wb = W1[(G_DIM + k) * H_DIM + j];
            #pragma unroll
            for (int r = 0; r < AB_ROWS; r++) {
                float gv = sg[r][k];
                accA[r] += gv * wa;
                accB[r] += gv * wb;
            }
        }
        #pragma unroll
        for (int r = 0; r < AB_ROWS; r++) {
            g_A[(n0 + r) * H_DIM + j] = accA[r];
            g_B[(n0 + r) * H_DIM + j] = accB[r];
        }
    }
}

// ---------------- main: mma.sync tf32 fused kernel ----------------
// CTA = 128 pairs = 2 spans, 256 threads = 8 warps (2 m-groups x 4 n-groups).
// Warp owns 4 m-tiles (16 rows each) x 5 n-tiles (8 cols each).
__global__ __launch_bounds__(256, 1) void main_kernel(
    const float* __restrict__ g_i, const float* __restrict__ ms,
    const float* __restrict__ W1, const float* __restrict__ W2,
    const float* __restrict__ b2,
    const int* __restrict__ mention_ids, const int* __restrict__ antecedent_ids,
    const int* __restrict__ distances, const int* __restrict__ genres,
    const int* __restrict__ speakers, const int* __restrict__ ant_counts,
    float* __restrict__ out)
{
    extern __shared__ __align__(16) char smem[];
    uint32_t* sProd = (uint32_t*)(smem + OFF_PROD);   // [128][PRDP], tf32 bits
    uint32_t* sWb   = (uint32_t*)(smem + OFF_WB);     // [4 kstep][160 n][4 t][2 h]
    float*    sAdd  = (float*)(smem + OFF_ADD);       // [128][ADDP]
    float*    sW2   = (float*)(smem + OFF_W2);        // [160]
    float*    sMS   = (float*)(smem + OFF_MS);        // [128]
    int*      sm_m  = (int*)(smem + OFF_M);
    int*      sm_a  = (int*)(smem + OFF_AI);
    float*    sPart = (float*)(smem + OFF_PART);      // [128][4]
    float*    sSc   = (float*)(smem + OFF_SC);        // [128]

    const int t    = threadIdx.x;
    const int w    = t >> 5;
    const int lane = t & 31;
    const int gidx = lane >> 2;   // groupID 0..7
    const int tig  = lane & 3;    // threadInGroup 0..3
    const int mg   = w >> 2;      // 0..1
    const int ng   = w & 3;       // 0..3
    const int pbase = blockIdx.x * 128;

    if (t < 128) {
        sm_m[t] = mention_ids[pbase + t];
        sm_a[t] = antecedent_ids[pbase + t];
    }
    if (t < NPAD) sW2[t] = (t < H_DIM) ? W2[t] : 0.f;
    __syncthreads();

    float acc[4][5][4];
    #pragma unroll
    for (int mt = 0; mt < 4; mt++)
        #pragma unroll
        for (int j = 0; j < 5; j++)
            #pragma unroll
            for (int e = 0; e < 4; e++) acc[mt][j][e] = 0.f;

    for (int c = 0; c < 16; c++) {
        const int kb = c * 32;
        __syncthreads();   // previous chunk's compute reads done

        // ---- stage W chunk in B-fragment layout (coalesced n-fast reads) ----
        for (int idx = t; idx < 32 * NPAD; idx += 256) {
            int kk = idx / NPAD, n = idx % NPAD;
            float v = (n < H_DIM) ? W1[(1024 + kb + kk) * H_DIM + n] : 0.f;
            int s = kk >> 3, kp = kk & 7;
            int tt = kp & 3, h = kp >> 2;
            sWb[(((s * NPAD) + n) * 4 + tt) * 2 + h] = f2tf32(v);
        }
        // ---- stage product tile [128 x 32] (tf32), float4 gathers ----
        for (int idx = t; idx < 1024; idx += 256) {
            int p = idx >> 3, q = idx & 7;
            const float4 mv = *(const float4*)(g_i + (size_t)sm_m[p] * G_DIM + kb + 4 * q);
            const float4 av = *(const float4*)(g_i + (size_t)sm_a[p] * G_DIM + kb + 4 * q);
            uint4 pr;
            pr.x = f2tf32(mv.x * av.x);
            pr.y = f2tf32(mv.y * av.y);
            pr.z = f2tf32(mv.z * av.z);
            pr.w = f2tf32(mv.w * av.w);
            *(uint4*)(sProd + p * PRDP + 4 * q) = pr;
        }
        // ---- stage Add rows [8c, 8c+8) ----
        for (int idx = t; idx < 8 * NPAD; idx += 256) {
            int pr = idx / NPAD, j = idx % NPAD;
            int p = 8 * c + pr;
            float v = 0.f;
            if (j < H_DIM) {
                int gp = pbase + p;
                int m = sm_m[p], a = sm_a[p];
                int d = distances[gp];
                int bkt = (d >= 1) + (d >= 2) + (d >= 3) + (d >= 4) +
                          (d >= 8) + (d >= 16) + (d >= 32) + (d >= 64);
                v = g_A[m * H_DIM + j] + g_B[a * H_DIM + j] + g_Ed[bkt * H_DIM + j] +
                    g_Eg[genres[gp] * H_DIM + j] + g_Es[speakers[gp] * H_DIM + j];
            }
            if (j < ADDP) sAdd[p * ADDP + j] = v;
        }
        if (t < 8) {
            int p = 8 * c + t;
            sMS[p] = ms[sm_m[p]] + ms[sm_a[p]] + b2[0];
        }
        __syncthreads();

        // ---- compute: 4 k-steps of m16n8k8 ----
        #pragma unroll
        for (int s = 0; s < 4; s++) {
            uint32_t afr[4][4];
            #pragma unroll
            for (int mt = 0; mt < 4; mt++) {
                int rb = 64 * mg + 16 * mt;
                const uint32_t* base = sProd + 8 * s + tig;
                afr[mt][0] = base[(rb + gidx) * PRDP];
                afr[mt][1] = base[(rb + gidx + 8) * PRDP];
                afr[mt][2] = base[(rb + gidx) * PRDP + 4];
                afr[mt][3] = base[(rb + gidx + 8) * PRDP + 4];
            }
            uint32_t bfr[5][2];
            #pragma unroll
            for (int j = 0; j < 5; j++) {
                int n = 8 * (5 * ng + j) + gidx;
                uint2 bv = *(const uint2*)(sWb + (((s * NPAD) + n) * 4 + tig) * 2);
                bfr[j][0] = bv.x; bfr[j][1] = bv.y;
            }
            #pragma unroll
            for (int mt = 0; mt < 4; mt++)
                #pragma unroll
                for (int j = 0; j < 5; j++)
                    mma_tf32(acc[mt][j], afr[mt], bfr[j]);
        }
    }
    __syncthreads();

    // ---- epilogue: + Add, ReLU, dot W2, partial per-row ----
    {
        float rp[4][2];
        #pragma unroll
        for (int mt = 0; mt < 4; mt++) { rp[mt][0] = 0.f; rp[mt][1] = 0.f; }
        #pragma unroll
        for (int mt = 0; mt < 4; mt++) {
            int rowA = 64 * mg + 16 * mt + gidx;
            int rowB = rowA + 8;
            #pragma unroll
            for (int j = 0; j < 5; j++) {
                int col0 = 8 * (5 * ng + j) + 2 * tig;
                float w0 = sW2[col0], w1 = sW2[col0 + 1];
                float h;
                h = acc[mt][j][0] + ((col0     < ADDP) ? sAdd[rowA * ADDP + col0]     : 0.f);
                rp[mt][0] += fmaxf(h, 0.f) * w0;
                h = acc[mt][j][1] + ((col0 + 1 < ADDP) ? sAdd[rowA * ADDP + col0 + 1] : 0.f);
                rp[mt][0] += fmaxf(h, 0.f) * w1;
                h = acc[mt][j][2] + ((col0     < ADDP) ? sAdd[rowB * ADDP + col0]     : 0.f);
                rp[mt][1] += fmaxf(h, 0.f) * w0;
                h = acc[mt][j][3] + ((col0 + 1 < ADDP) ? sAdd[rowB * ADDP + col0 + 1] : 0.f);
                rp[mt][1] += fmaxf(h, 0.f) * w1;
            }
        }
        // reduce over the 4 lanes of each group (tig)
        #pragma unroll
        for (int off = 1; off <= 2; off <<= 1)
            #pragma unroll
            for (int mt = 0; mt < 4; mt++) {
                rp[mt][0] += __shfl_xor_sync(0xffffffffu, rp[mt][0], off);
                rp[mt][1] += __shfl_xor_sync(0xffffffffu, rp[mt][1], off);
            }
        if (tig == 0) {
            #pragma unroll
            for (int mt = 0; mt < 4; mt++) {
                int rowA = 64 * mg + 16 * mt + gidx;
                sPart[rowA * 4 + ng]       = rp[mt][0];
                sPart[(rowA + 8) * 4 + ng] = rp[mt][1];
            }
        }
    }
    __syncthreads();
    if (t < 128)
        sSc[t] = sPart[t * 4 + 0] + sPart[t * 4 + 1] + sPart[t * 4 + 2] + sPart[t * 4 + 3] + sMS[t];
    __syncthreads();

    // ---- fused per-span softmax (2 spans per CTA) ----
    if (w < 2) {
        int s = blockIdx.x * 2 + w;
        int cnt = ant_counts[s];
        float v0 = sSc[w * 64 + lane], v1 = sSc[w * 64 + lane + 32];
        bool val0 = lane < cnt, val1 = (lane + 32) < cnt;
        float mx = 0.f;  // epsilon logit = 0
        if (val0) mx = fmaxf(mx, v0);
        if (val1) mx = fmaxf(mx, v1);
        #pragma unroll
        for (int off = 16; off >= 1; off >>= 1)
            mx = fmaxf(mx, __shfl_xor_sync(0xffffffffu, mx, off));
        float e0 = val0 ? expf(v0 - mx) : 0.f;
        float e1 = val1 ? expf(v1 - mx) : 0.f;
        float sum = e0 + e1;
        #pragma unroll
        for (int off = 16; off >= 1; off >>= 1)
            sum += __shfl_xor_sync(0xffffffffu, sum, off);
        float eps = expf(-mx);
        sum += eps;
        float inv = 1.0f / sum;
        float* orow = out + (size_t)s * (K_ANT + 1);
        orow[lane]      = val0 ? e0 * inv : 1000.0f;
        orow[lane + 32] = val1 ? e1 * inv : 1000.0f;
        if (lane == 0) orow[K_ANT] = eps * inv;
    }
}

extern "C" void kernel_launch(void* const* d_in, const int* in_sizes, int n_in,
                              void* d_out, int out_size) {
    const float* g_i            = (const float*)d_in[0];
    const float* mention_scores = (const float*)d_in[1];
    const float* dist_embed     = (const float*)d_in[2];
    const float* genre_embed    = (const float*)d_in[3];
    const float* speaker_embed  = (const float*)d_in[4];
    const float* W1             = (const float*)d_in[5];
    const float* b1             = (const float*)d_in[6];
    const float* W2             = (const float*)d_in[7];
    const float* b2             = (const float*)d_in[8];
    const int*   mention_ids    = (const int*)d_in[9];
    const int*   antecedent_ids = (const int*)d_in[10];
    const int*   distances      = (const int*)d_in[11];
    const int*   genres         = (const int*)d_in[12];
    const int*   speakers       = (const int*)d_in[13];
    const int*   ant_counts     = (const int*)d_in[14];
    float* out = (float*)d_out;

    cudaFuncSetAttribute(main_kernel, cudaFuncAttributeMaxDynamicSharedMemorySize, SMEM_TOTAL);

    tables_kernel<<<(20 * H_DIM + 255) / 256, 256>>>(dist_embed, genre_embed,
                                                     speaker_embed, W1, b1);
    ab_kernel<<<N_MENT / AB_ROWS, 160>>>(g_i, W1);
    main_kernel<<<S_SPANS / 2, 256, SMEM_TOTAL>>>(g_i, mention_scores, W1, W2, b2,
                                                  mention_ids, antecedent_ids, distances,
                                                  genres, speakers, ant_counts, out);
}

// round 9
// speedup vs baseline: 1.7905x; 1.4175x over previous
#include <cuda_runtime.h>
#include <cstdint>

#define S_SPANS 4096
#define K_ANT   64
#define N_MENT  4096
#define G_DIM   512
#define H_DIM   150
#define NPAD    160
#define AB_ROWS 16

#define ADDP 153   // sAdd row stride (floats)
#define MPRD 36    // sM/sA row stride (floats): A-frag bank = 4*gidx+tig, conflict-free
#define WSTR 168   // sW row stride (uint32): B-frag bank = 8*tig+gidx, conflict-free

// ---------------- scratch (device globals; no allocation) ----------------
__device__ float g_A[N_MENT * H_DIM];      // g_i @ W1[0:512]
__device__ float g_B[N_MENT * H_DIM];      // g_i @ W1[512:1024]
__device__ float g_Ed[10 * H_DIM];         // dist_embed @ W1[1536:1556] + b1
__device__ float g_Eg[7 * H_DIM];          // genre_embed @ W1[1556:1576]
__device__ float g_Es[3 * H_DIM];          // speaker_embed @ W1[1576:1596]
__device__ uint32_t g_Wp[G_DIM * NPAD];    // W1[1024:1536] padded->[512][160], tf32 bits

// ---------------- SMEM layout (bytes) ----------------
#define SZ_MA   18432                       // 128*36*4
#define SZ_W    21504                       // 32*168*4
#define OFF_M0  0                           // 2 buffers
#define OFF_A0  36864                       // 2 buffers
#define OFF_W0  73728                       // 2 buffers
#define OFF_ADD 116736                      // 128*153*4 = 78336
#define OFF_W2  195072                      // 160*4
#define OFF_MS  195712                      // 128*4
#define OFF_MID 196224                      // 128*4
#define OFF_AID 196736                      // 128*4
#define OFF_PT  197248                      // 128*4*4
#define OFF_SC  199296                      // 128*4
#define SMEM_TOTAL 199808

__device__ __forceinline__ uint32_t f2tf32(float f) {
    uint32_t u;
    asm("cvt.rna.tf32.f32 %0, %1;" : "=r"(u) : "f"(f));
    return u;
}
__device__ __forceinline__ uint32_t smem_u32(const void* p) {
    uint32_t a;
    asm("{ .reg .u64 t; cvta.to.shared.u64 t, %1; cvt.u32.u64 %0, t; }" : "=r"(a) : "l"(p));
    return a;
}
__device__ __forceinline__ void cp16(uint32_t dst, const void* src) {
    asm volatile("cp.async.cg.shared.global [%0], [%1], 16;" :: "r"(dst), "l"(src) : "memory");
}
#define CP_COMMIT() asm volatile("cp.async.commit_group;" ::: "memory")
#define CP_WAIT1()  asm volatile("cp.async.wait_group 1;" ::: "memory")

__device__ __forceinline__ void mma_tf32(float* d, const uint32_t* a, const uint32_t* b) {
    asm volatile(
        "mma.sync.aligned.m16n8k8.row.col.f32.tf32.tf32.f32 "
        "{%0,%1,%2,%3}, {%4,%5,%6,%7}, {%8,%9}, {%0,%1,%2,%3};"
        : "+f"(d[0]), "+f"(d[1]), "+f"(d[2]), "+f"(d[3])
        : "r"(a[0]), "r"(a[1]), "r"(a[2]), "r"(a[3]), "r"(b[0]), "r"(b[1]));
}

// ---------------- tiny tables ----------------
__global__ void tables_kernel(const float* __restrict__ dist_embed,
                              const float* __restrict__ genre_embed,
                              const float* __restrict__ speaker_embed,
                              const float* __restrict__ W1,
                              const float* __restrict__ b1) {
    int idx = blockIdx.x * blockDim.x + threadIdx.x;
    if (idx < 10 * H_DIM) {
        int d = idx / H_DIM, j = idx % H_DIM;
        float acc = b1[j];
        #pragma unroll
        for (int t = 0; t < 20; t++)
            acc += dist_embed[d * 20 + t] * W1[(1536 + t) * H_DIM + j];
        g_Ed[idx] = acc;
    } else if (idx < 17 * H_DIM) {
        int r = idx - 10 * H_DIM;
        int d = r / H_DIM, j = r % H_DIM;
        float acc = 0.f;
        #pragma unroll
        for (int t = 0; t < 20; t++)
            acc += genre_embed[d * 20 + t] * W1[(1556 + t) * H_DIM + j];
        g_Eg[r] = acc;
    } else if (idx < 20 * H_DIM) {
        int r = idx - 17 * H_DIM;
        int d = r / H_DIM, j = r % H_DIM;
        float acc = 0.f;
        #pragma unroll
        for (int t = 0; t < 20; t++)
            acc += speaker_embed[d * 20 + t] * W1[(1576 + t) * H_DIM + j];
        g_Es[r] = acc;
    }
}

// ---------------- W pack: [512][150] -> [512][160] tf32 bits ----------------
__global__ void packw_kernel(const float* __restrict__ W1) {
    int idx = blockIdx.x * blockDim.x + threadIdx.x;
    if (idx < G_DIM * NPAD) {
        int k = idx / NPAD, n = idx % NPAD;
        float v = (n < H_DIM) ? W1[(1024 + k) * H_DIM + n] : 0.f;
        g_Wp[idx] = f2tf32(v);
    }
}

// ---------------- A/B precompute ----------------
__global__ __launch_bounds__(160) void ab_kernel(const float* __restrict__ g_i,
                                                 const float* __restrict__ W1) {
    __shared__ float sg[AB_ROWS][G_DIM];
    int n0 = blockIdx.x * AB_ROWS;
    for (int idx = threadIdx.x; idx < AB_ROWS * G_DIM; idx += blockDim.x) {
        int r = idx / G_DIM, k = idx % G_DIM;
        sg[r][k] = g_i[(n0 + r) * G_DIM + k];
    }
    __syncthreads();
    int j = threadIdx.x;
    if (j < H_DIM) {
        float accA[AB_ROWS], accB[AB_ROWS];
        #pragma unroll
        for (int r = 0; r < AB_ROWS; r++) { accA[r] = 0.f; accB[r] = 0.f; }
        for (int k = 0; k < G_DIM; k++) {
            float wa = W1[k * H_DIM + j];
            float wb = W1[(G_DIM + k) * H_DIM + j];
            #pragma unroll
            for (int r = 0; r < AB_ROWS; r++) {
                float gv = sg[r][k];
                accA[r] += gv * wa;
                accB[r] += gv * wb;
            }
        }
        #pragma unroll
        for (int r = 0; r < AB_ROWS; r++) {
            g_A[(n0 + r) * H_DIM + j] = accA[r];
            g_B[(n0 + r) * H_DIM + j] = accB[r];
        }
    }
}

// ---------------- main: cp.async-pipelined mma.sync tf32 fused kernel ----------------
// CTA = 128 pairs = 2 spans, 256 threads = 8 warps (2 m-groups x 4 n-groups).
// Warp owns 4 m-tiles (16 rows) x 5 n-tiles (8 cols). K = 16 chunks of 32, 2-stage pipeline.
__global__ __launch_bounds__(256, 1) void main_kernel(
    const float* __restrict__ g_i, const float* __restrict__ ms,
    const float* __restrict__ W2, const float* __restrict__ b2,
    const int* __restrict__ mention_ids, const int* __restrict__ antecedent_ids,
    const int* __restrict__ distances, const int* __restrict__ genres,
    const int* __restrict__ speakers, const int* __restrict__ ant_counts,
    float* __restrict__ out)
{
    extern __shared__ __align__(16) char smem[];
    const uint32_t sbase = smem_u32(smem);
    float*    sAdd = (float*)(smem + OFF_ADD);
    float*    sW2  = (float*)(smem + OFF_W2);
    float*    sMS  = (float*)(smem + OFF_MS);
    int*      sm_m = (int*)(smem + OFF_MID);
    int*      sm_a = (int*)(smem + OFF_AID);
    float*    sPt  = (float*)(smem + OFF_PT);
    float*    sSc  = (float*)(smem + OFF_SC);

    const int t    = threadIdx.x;
    const int w    = t >> 5;
    const int lane = t & 31;
    const int gidx = lane >> 2;
    const int tig  = lane & 3;
    const int mg   = w >> 2;
    const int ng   = w & 3;
    const int pbase = blockIdx.x * 128;

    if (t < 128) {
        sm_m[t] = mention_ids[pbase + t];
        sm_a[t] = antecedent_ids[pbase + t];
    }
    if (t < NPAD) sW2[t] = (t < H_DIM) ? W2[t] : 0.f;
    __syncthreads();

    // ---- per-thread cp.async slot pointers (fixed across chunks) ----
    const float* srcM[4];
    const float* srcA[4];
    uint32_t dMA[4];
    #pragma unroll
    for (int i = 0; i < 4; i++) {
        int idx = t + 256 * i;
        int p = idx >> 3, q = idx & 7;
        srcM[i] = g_i + (size_t)sm_m[p] * G_DIM + 4 * q;
        srcA[i] = g_i + (size_t)sm_a[p] * G_DIM + 4 * q;
        dMA[i]  = (uint32_t)(p * MPRD + 4 * q) * 4u;
    }
    const uint32_t* srcW[5];
    uint32_t dW[5];
    #pragma unroll
    for (int i = 0; i < 5; i++) {
        int idx = t + 256 * i;
        int kk = idx / 40, c16 = idx % 40;
        srcW[i] = g_Wp + kk * NPAD + 4 * c16;
        dW[i]   = (uint32_t)(kk * WSTR + 4 * c16) * 4u;
    }

    // ---- prologue: prefetch chunks 0,1 ----
    #pragma unroll
    for (int b = 0; b < 2; b++) {
        #pragma unroll
        for (int i = 0; i < 4; i++) {
            cp16(sbase + OFF_M0 + b * SZ_MA + dMA[i], srcM[i] + b * 32);
            cp16(sbase + OFF_A0 + b * SZ_MA + dMA[i], srcA[i] + b * 32);
        }
        #pragma unroll
        for (int i = 0; i < 5; i++)
            cp16(sbase + OFF_W0 + b * SZ_W + dW[i], srcW[i] + b * 32 * NPAD);
        CP_COMMIT();
    }

    float acc[4][5][4];
    #pragma unroll
    for (int mt = 0; mt < 4; mt++)
        #pragma unroll
        for (int j = 0; j < 5; j++)
            #pragma unroll
            for (int e = 0; e < 4; e++) acc[mt][j][e] = 0.f;

    for (int c = 0; c < 16; c++) {
        const int b = c & 1;
        const float*    pM = (const float*)(smem + OFF_M0 + b * SZ_MA);
        const float*    pA = (const float*)(smem + OFF_A0 + b * SZ_MA);
        const uint32_t* pW = (const uint32_t*)(smem + OFF_W0 + b * SZ_W);

        CP_WAIT1();
        __syncthreads();

        // ---- compute: 4 k-steps of m16n8k8, product formed in registers ----
        #pragma unroll
        for (int s = 0; s < 4; s++) {
            uint32_t afr[4][4];
            #pragma unroll
            for (int mt = 0; mt < 4; mt++) {
                int r0 = (64 * mg + 16 * mt + gidx) * MPRD + 8 * s + tig;
                int r1 = r0 + 8 * MPRD;
                afr[mt][0] = f2tf32(pM[r0]     * pA[r0]);
                afr[mt][1] = f2tf32(pM[r1]     * pA[r1]);
                afr[mt][2] = f2tf32(pM[r0 + 4] * pA[r0 + 4]);
                afr[mt][3] = f2tf32(pM[r1 + 4] * pA[r1 + 4]);
            }
            uint32_t bfr[5][2];
            #pragma unroll
            for (int j = 0; j < 5; j++) {
                int n = 8 * (5 * ng + j) + gidx;
                bfr[j][0] = pW[(8 * s + tig) * WSTR + n];
                bfr[j][1] = pW[(8 * s + tig + 4) * WSTR + n];
            }
            #pragma unroll
            for (int mt = 0; mt < 4; mt++)
                #pragma unroll
                for (int j = 0; j < 5; j++)
                    mma_tf32(acc[mt][j], afr[mt], bfr[j]);
        }

        // ---- Add-gather rows [8c, 8c+8) (latency drains into next chunk's wait) ----
        #pragma unroll 1
        for (int idx = t; idx < 8 * NPAD; idx += 256) {
            int pr = idx / NPAD, j = idx % NPAD;
            int p = 8 * c + pr;
            float v = 0.f;
            if (j < H_DIM) {
                int gp = pbase + p;
                int m = sm_m[p], a = sm_a[p];
                int d = distances[gp];
                int bkt = (d >= 1) + (d >= 2) + (d >= 3) + (d >= 4) +
                          (d >= 8) + (d >= 16) + (d >= 32) + (d >= 64);
                v = g_A[m * H_DIM + j] + g_B[a * H_DIM + j] + g_Ed[bkt * H_DIM + j] +
                    g_Eg[genres[gp] * H_DIM + j] + g_Es[speakers[gp] * H_DIM + j];
            }
            if (j < ADDP) sAdd[p * ADDP + j] = v;
        }
        if (t < 8) {
            int p = 8 * c + t;
            sMS[p] = ms[sm_m[p]] + ms[sm_a[p]] + b2[0];
        }

        __syncthreads();   // all reads of buffer b finished

        // ---- prefetch chunk c+2 into buffer b ----
        if (c + 2 < 16) {
            const int cc = c + 2;
            #pragma unroll
            for (int i = 0; i < 4; i++) {
                cp16(sbase + OFF_M0 + b * SZ_MA + dMA[i], srcM[i] + cc * 32);
                cp16(sbase + OFF_A0 + b * SZ_MA + dMA[i], srcA[i] + cc * 32);
            }
            #pragma unroll
            for (int i = 0; i < 5; i++)
                cp16(sbase + OFF_W0 + b * SZ_W + dW[i], srcW[i] + cc * 32 * NPAD);
        }
        CP_COMMIT();
    }
    __syncthreads();

    // ---- epilogue: + Add, ReLU, dot W2 ----
    {
        float rp[4][2];
        #pragma unroll
        for (int mt = 0; mt < 4; mt++) { rp[mt][0] = 0.f; rp[mt][1] = 0.f; }
        #pragma unroll
        for (int mt = 0; mt < 4; mt++) {
            int rowA = 64 * mg + 16 * mt + gidx;
            int rowB = rowA + 8;
            #pragma unroll
            for (int j = 0; j < 5; j++) {
                int col0 = 8 * (5 * ng + j) + 2 * tig;
                float w0 = sW2[col0], w1 = sW2[col0 + 1];
                float h;
                h = acc[mt][j][0] + ((col0     < ADDP) ? sAdd[rowA * ADDP + col0]     : 0.f);
                rp[mt][0] += fmaxf(h, 0.f) * w0;
                h = acc[mt][j][1] + ((col0 + 1 < ADDP) ? sAdd[rowA * ADDP + col0 + 1] : 0.f);
                rp[mt][0] += fmaxf(h, 0.f) * w1;
                h = acc[mt][j][2] + ((col0     < ADDP) ? sAdd[rowB * ADDP + col0]     : 0.f);
                rp[mt][1] += fmaxf(h, 0.f) * w0;
                h = acc[mt][j][3] + ((col0 + 1 < ADDP) ? sAdd[rowB * ADDP + col0 + 1] : 0.f);
                rp[mt][1] += fmaxf(h, 0.f) * w1;
            }
        }
        #pragma unroll
        for (int off = 1; off <= 2; off <<= 1)
            #pragma unroll
            for (int mt = 0; mt < 4; mt++) {
                rp[mt][0] += __shfl_xor_sync(0xffffffffu, rp[mt][0], off);
                rp[mt][1] += __shfl_xor_sync(0xffffffffu, rp[mt][1], off);
            }
        if (tig == 0) {
            #pragma unroll
            for (int mt = 0; mt < 4; mt++) {
                int rowA = 64 * mg + 16 * mt + gidx;
                sPt[rowA * 4 + ng]       = rp[mt][0];
                sPt[(rowA + 8) * 4 + ng] = rp[mt][1];
            }
        }
    }
    __syncthreads();
    if (t < 128)
        sSc[t] = sPt[t * 4 + 0] + sPt[t * 4 + 1] + sPt[t * 4 + 2] + sPt[t * 4 + 3] + sMS[t];
    __syncthreads();

    // ---- fused per-span softmax (2 spans per CTA) ----
    if (w < 2) {
        int s = blockIdx.x * 2 + w;
        int cnt = ant_counts[s];
        float v0 = sSc[w * 64 + lane], v1 = sSc[w * 64 + lane + 32];
        bool val0 = lane < cnt, val1 = (lane + 32) < cnt;
        float mx = 0.f;  // epsilon logit = 0
        if (val0) mx = fmaxf(mx, v0);
        if (val1) mx = fmaxf(mx, v1);
        #pragma unroll
        for (int off = 16; off >= 1; off >>= 1)
            mx = fmaxf(mx, __shfl_xor_sync(0xffffffffu, mx, off));
        float e0 = val0 ? expf(v0 - mx) : 0.f;
        float e1 = val1 ? expf(v1 - mx) : 0.f;
        float sum = e0 + e1;
        #pragma unroll
        for (int off = 16; off >= 1; off >>= 1)
            sum += __shfl_xor_sync(0xffffffffu, sum, off);
        float eps = expf(-mx);
        sum += eps;
        float inv = 1.0f / sum;
        float* orow = out + (size_t)s * (K_ANT + 1);
        orow[lane]      = val0 ? e0 * inv : 1000.0f;
        orow[lane + 32] = val1 ? e1 * inv : 1000.0f;
        if (lane == 0) orow[K_ANT] = eps * inv;
    }
}

extern "C" void kernel_launch(void* const* d_in, const int* in_sizes, int n_in,
                              void* d_out, int out_size) {
    const float* g_i            = (const float*)d_in[0];
    const float* mention_scores = (const float*)d_in[1];
    const float* dist_embed     = (const float*)d_in[2];
    const float* genre_embed    = (const float*)d_in[3];
    const float* speaker_embed  = (const float*)d_in[4];
    const float* W1             = (const float*)d_in[5];
    const float* b1             = (const float*)d_in[6];
    const float* W2             = (const float*)d_in[7];
    const float* b2             = (const float*)d_in[8];
    const int*   mention_ids    = (const int*)d_in[9];
    const int*   antecedent_ids = (const int*)d_in[10];
    const int*   distances      = (const int*)d_in[11];
    const int*   genres         = (const int*)d_in[12];
    const int*   speakers       = (const int*)d_in[13];
    const int*   ant_counts     = (const int*)d_in[14];
    float* out = (float*)d_out;

    cudaFuncSetAttribute(main_kernel, cudaFuncAttributeMaxDynamicSharedMemorySize, SMEM_TOTAL);

    tables_kernel<<<(20 * H_DIM + 255) / 256, 256>>>(dist_embed, genre_embed,
                                                     speaker_embed, W1, b1);
    packw_kernel<<<(G_DIM * NPAD + 255) / 256, 256>>>(W1);
    ab_kernel<<<N_MENT / AB_ROWS, 160>>>(g_i, W1);
    main_kernel<<<S_SPANS / 2, 256, SMEM_TOTAL>>>(g_i, mention_scores, W2, b2,
                                                  mention_ids, antecedent_ids, distances,
                                                  genres, speakers, ant_counts, out);
}

// round 11
// speedup vs baseline: 2.0206x; 1.1285x over previous
#include <cuda_runtime.h>
#include <cstdint>

#define S_SPANS 4096
#define K_ANT   64
#define N_MENT  4096
#define G_DIM   512
#define H_DIM   150
#define NPAD    160
#define AB_ROWS 16

#define ADDP 153   // sAdd row stride (floats)
#define MPRD 36    // sM/sA row stride (floats): A-frag bank = 4*gidx+tig, conflict-free
#define WSTR 168   // sW row stride (uint32): B-frag bank = 8*tig+gidx, conflict-free

// ---------------- scratch (device globals; no allocation) ----------------
__device__ float g_A[N_MENT * H_DIM];      // g_i @ W1[0:512]
__device__ float g_B[N_MENT * H_DIM];      // g_i @ W1[512:1024]
__device__ float g_Ed[10 * H_DIM];         // dist_embed @ W1[1536:1556] + b1
__device__ float g_Eg[7 * H_DIM];          // genre_embed @ W1[1556:1576]
__device__ float g_Es[3 * H_DIM];          // speaker_embed @ W1[1576:1596]
__device__ uint32_t g_Wp[G_DIM * NPAD];    // W1[1024:1536] padded->[512][160], tf32 bits

// ---------------- SMEM layout (bytes) ----------------
#define SZ_MA   18432                       // 128*36*4
#define SZ_W    21504                       // 32*168*4
#define OFF_M0  0                           // 2 buffers
#define OFF_A0  36864                       // 2 buffers
#define OFF_W0  73728                       // 2 buffers
#define OFF_ADD 116736                      // 128*153*4 = 78336
#define OFF_W2  195072                      // 160*4
#define OFF_MS  195712                      // 128*4
#define OFF_MID 196224                      // 128*4
#define OFF_AID 196736                      // 128*4
#define OFF_PT  197248                      // 128*4*4
#define OFF_SC  199296                      // 128*4
#define SMEM_TOTAL 199808

__device__ __forceinline__ uint32_t f2tf32(float f) {
    uint32_t u;
    asm("cvt.rna.tf32.f32 %0, %1;" : "=r"(u) : "f"(f));
    return u;
}
__device__ __forceinline__ uint32_t smem_u32(const void* p) {
    uint32_t a;
    asm("{ .reg .u64 t; cvta.to.shared.u64 t, %1; cvt.u32.u64 %0, t; }" : "=r"(a) : "l"(p));
    return a;
}
__device__ __forceinline__ void cp16(uint32_t dst, const void* src) {
    asm volatile("cp.async.cg.shared.global [%0], [%1], 16;" :: "r"(dst), "l"(src) : "memory");
}
#define CP_COMMIT() asm volatile("cp.async.commit_group;" ::: "memory")
#define CP_WAIT1()  asm volatile("cp.async.wait_group 1;" ::: "memory")

__device__ __forceinline__ void mma_tf32(float* d, const uint32_t* a, const uint32_t* b) {
    asm volatile(
        "mma.sync.aligned.m16n8k8.row.col.f32.tf32.tf32.f32 "
        "{%0,%1,%2,%3}, {%4,%5,%6,%7}, {%8,%9}, {%0,%1,%2,%3};"
        : "+f"(d[0]), "+f"(d[1]), "+f"(d[2]), "+f"(d[3])
        : "r"(a[0]), "r"(a[1]), "r"(a[2]), "r"(a[3]), "r"(b[0]), "r"(b[1]));
}

// ---------------- tiny tables ----------------
__global__ void tables_kernel(const float* __restrict__ dist_embed,
                              const float* __restrict__ genre_embed,
                              const float* __restrict__ speaker_embed,
                              const float* __restrict__ W1,
                              const float* __restrict__ b1) {
    int idx = blockIdx.x * blockDim.x + threadIdx.x;
    if (idx < 10 * H_DIM) {
        int d = idx / H_DIM, j = idx % H_DIM;
        float acc = b1[j];
        #pragma unroll
        for (int t = 0; t < 20; t++)
            acc += dist_embed[d * 20 + t] * W1[(1536 + t) * H_DIM + j];
        g_Ed[idx] = acc;
    } else if (idx < 17 * H_DIM) {
        int r = idx - 10 * H_DIM;
        int d = r / H_DIM, j = r % H_DIM;
        float acc = 0.f;
        #pragma unroll
        for (int t = 0; t < 20; t++)
            acc += genre_embed[d * 20 + t] * W1[(1556 + t) * H_DIM + j];
        g_Eg[r] = acc;
    } else if (idx < 20 * H_DIM) {
        int r = idx - 17 * H_DIM;
        int d = r / H_DIM, j = r % H_DIM;
        float acc = 0.f;
        #pragma unroll
        for (int t = 0; t < 20; t++)
            acc += speaker_embed[d * 20 + t] * W1[(1576 + t) * H_DIM + j];
        g_Es[r] = acc;
    }
}

// ---------------- W pack: [512][150] -> [512][160] tf32 bits ----------------
__global__ void packw_kernel(const float* __restrict__ W1) {
    int idx = blockIdx.x * blockDim.x + threadIdx.x;
    if (idx < G_DIM * NPAD) {
        int k = idx / NPAD, n = idx % NPAD;
        float v = (n < H_DIM) ? W1[(1024 + k) * H_DIM + n] : 0.f;
        g_Wp[idx] = f2tf32(v);
    }
}

// ---------------- A/B precompute ----------------
__global__ __launch_bounds__(160) void ab_kernel(const float* __restrict__ g_i,
                                                 const float* __restrict__ W1) {
    __shared__ float sg[AB_ROWS][G_DIM];
    int n0 = blockIdx.x * AB_ROWS;
    for (int idx = threadIdx.x; idx < AB_ROWS * G_DIM; idx += blockDim.x) {
        int r = idx / G_DIM, k = idx % G_DIM;
        sg[r][k] = g_i[(n0 + r) * G_DIM + k];
    }
    __syncthreads();
    int j = threadIdx.x;
    if (j < H_DIM) {
        float accA[AB_ROWS], accB[AB_ROWS];
        #pragma unroll
        for (int r = 0; r < AB_ROWS; r++) { accA[r] = 0.f; accB[r] = 0.f; }
        for (int k = 0; k < G_DIM; k++) {
            float wa = W1[k * H_DIM + j];
            float wb = W1[(G_DIM + k) * H_DIM + j];
            #pragma unroll
            for (int r = 0; r < AB_ROWS; r++) {
                float gv = sg[r][k];
                accA[r] += gv * wa;
                accB[r] += gv * wb;
            }
        }
        #pragma unroll
        for (int r = 0; r < AB_ROWS; r++) {
            g_A[(n0 + r) * H_DIM + j] = accA[r];
            g_B[(n0 + r) * H_DIM + j] = accB[r];
        }
    }
}

// ---------------- main: cp.async-pipelined mma.sync tf32 fused kernel ----------------
// CTA = 128 pairs = 2 spans, 512 threads = 16 warps (4 m-groups x 4 n-groups).
// Warp owns 2 m-tiles (16 rows) x 5 n-tiles (8 cols). K = 16 chunks of 32, 2-stage pipeline.
__global__ __launch_bounds__(512, 1) void main_kernel(
    const float* __restrict__ g_i, const float* __restrict__ ms,
    const float* __restrict__ W2, const float* __restrict__ b2,
    const int* __restrict__ mention_ids, const int* __restrict__ antecedent_ids,
    const int* __restrict__ distances, const int* __restrict__ genres,
    const int* __restrict__ speakers, const int* __restrict__ ant_counts,
    float* __restrict__ out)
{
    extern __shared__ __align__(16) char smem[];
    const uint32_t sbase = smem_u32(smem);
    float*    sAdd = (float*)(smem + OFF_ADD);
    float*    sW2  = (float*)(smem + OFF_W2);
    float*    sMS  = (float*)(smem + OFF_MS);
    int*      sm_m = (int*)(smem + OFF_MID);
    int*      sm_a = (int*)(smem + OFF_AID);
    float*    sPt  = (float*)(smem + OFF_PT);
    float*    sSc  = (float*)(smem + OFF_SC);

    const int t    = threadIdx.x;
    const int w    = t >> 5;
    const int lane = t & 31;
    const int gidx = lane >> 2;
    const int tig  = lane & 3;
    const int mg   = w >> 2;      // 0..3, 32 rows each
    const int ng   = w & 3;       // 0..3, 40 cols each
    const int pbase = blockIdx.x * 128;

    if (t < 128) {
        sm_m[t] = mention_ids[pbase + t];
        sm_a[t] = antecedent_ids[pbase + t];
    }
    if (t < NPAD) sW2[t] = (t < H_DIM) ? W2[t] : 0.f;
    __syncthreads();

    // ---- per-thread cp.async slot pointers (fixed across chunks) ----
    const float* srcM[2];
    const float* srcA[2];
    uint32_t dMA[2];
    #pragma unroll
    for (int i = 0; i < 2; i++) {
        int idx = t + 512 * i;
        int p = idx >> 3, q = idx & 7;
        srcM[i] = g_i + (size_t)sm_m[p] * G_DIM + 4 * q;
        srcA[i] = g_i + (size_t)sm_a[p] * G_DIM + 4 * q;
        dMA[i]  = (uint32_t)(p * MPRD + 4 * q) * 4u;
    }
    const uint32_t* srcW[3];
    uint32_t dW[3];
    bool vW[3];
    #pragma unroll
    for (int i = 0; i < 3; i++) {
        int idx = t + 512 * i;
        vW[i] = idx < 1280;
        int cidx = vW[i] ? idx : 0;
        int kk = cidx / 40, c16 = cidx % 40;
        srcW[i] = g_Wp + kk * NPAD + 4 * c16;
        dW[i]   = (uint32_t)(kk * WSTR + 4 * c16) * 4u;
    }

    // ---- prologue: prefetch chunks 0,1 ----
    #pragma unroll
    for (int b = 0; b < 2; b++) {
        #pragma unroll
        for (int i = 0; i < 2; i++) {
            cp16(sbase + OFF_M0 + b * SZ_MA + dMA[i], srcM[i] + b * 32);
            cp16(sbase + OFF_A0 + b * SZ_MA + dMA[i], srcA[i] + b * 32);
        }
        #pragma unroll
        for (int i = 0; i < 3; i++)
            if (vW[i]) cp16(sbase + OFF_W0 + b * SZ_W + dW[i], srcW[i] + b * 32 * NPAD);
        CP_COMMIT();
    }

    float acc[2][5][4];
    #pragma unroll
    for (int mt = 0; mt < 2; mt++)
        #pragma unroll
        for (int j = 0; j < 5; j++)
            #pragma unroll
            for (int e = 0; e < 4; e++) acc[mt][j][e] = 0.f;

    for (int c = 0; c < 16; c++) {
        const int b = c & 1;
        const float*    pM = (const float*)(smem + OFF_M0 + b * SZ_MA);
        const float*    pA = (const float*)(smem + OFF_A0 + b * SZ_MA);
        const uint32_t* pW = (const uint32_t*)(smem + OFF_W0 + b * SZ_W);

        CP_WAIT1();
        __syncthreads();

        // ---- compute: 4 k-steps of m16n8k8, product formed in registers ----
        #pragma unroll
        for (int s = 0; s < 4; s++) {
            uint32_t afr[2][4];
            #pragma unroll
            for (int mt = 0; mt < 2; mt++) {
                int r0 = (32 * mg + 16 * mt + gidx) * MPRD + 8 * s + tig;
                int r1 = r0 + 8 * MPRD;
                afr[mt][0] = f2tf32(pM[r0]     * pA[r0]);
                afr[mt][1] = f2tf32(pM[r1]     * pA[r1]);
                afr[mt][2] = f2tf32(pM[r0 + 4] * pA[r0 + 4]);
                afr[mt][3] = f2tf32(pM[r1 + 4] * pA[r1 + 4]);
            }
            uint32_t bfr[5][2];
            #pragma unroll
            for (int j = 0; j < 5; j++) {
                int n = 8 * (5 * ng + j) + gidx;
                bfr[j][0] = pW[(8 * s + tig) * WSTR + n];
                bfr[j][1] = pW[(8 * s + tig + 4) * WSTR + n];
            }
            #pragma unroll
            for (int mt = 0; mt < 2; mt++)
                #pragma unroll
                for (int j = 0; j < 5; j++)
                    mma_tf32(acc[mt][j], afr[mt], bfr[j]);
        }

        // ---- Add-gather rows [8c, 8c+8) (latency drains into next chunk's wait) ----
        #pragma unroll 1
        for (int idx = t; idx < 8 * NPAD; idx += 512) {
            int pr = idx / NPAD, j = idx % NPAD;
            int p = 8 * c + pr;
            float v = 0.f;
            if (j < H_DIM) {
                int gp = pbase + p;
                int m = sm_m[p], a = sm_a[p];
                int d = distances[gp];
                int bkt = (d >= 1) + (d >= 2) + (d >= 3) + (d >= 4) +
                          (d >= 8) + (d >= 16) + (d >= 32) + (d >= 64);
                v = g_A[m * H_DIM + j] + g_B[a * H_DIM + j] + g_Ed[bkt * H_DIM + j] +
                    g_Eg[genres[gp] * H_DIM + j] + g_Es[speakers[gp] * H_DIM + j];
            }
            if (j < ADDP) sAdd[p * ADDP + j] = v;
        }
        if (t < 8) {
            int p = 8 * c + t;
            sMS[p] = ms[sm_m[p]] + ms[sm_a[p]] + b2[0];
        }

        __syncthreads();   // all reads of buffer b finished

        // ---- prefetch chunk c+2 into buffer b ----
        if (c + 2 < 16) {
            const int cc = c + 2;
            #pragma unroll
            for (int i = 0; i < 2; i++) {
                cp16(sbase + OFF_M0 + b * SZ_MA + dMA[i], srcM[i] + cc * 32);
                cp16(sbase + OFF_A0 + b * SZ_MA + dMA[i], srcA[i] + cc * 32);
            }
            #pragma unroll
            for (int i = 0; i < 3; i++)
                if (vW[i]) cp16(sbase + OFF_W0 + b * SZ_W + dW[i], srcW[i] + cc * 32 * NPAD);
        }
        CP_COMMIT();
    }
    __syncthreads();

    // ---- epilogue: + Add, ReLU, dot W2 ----
    {
        float rp[2][2];
        #pragma unroll
        for (int mt = 0; mt < 2; mt++) { rp[mt][0] = 0.f; rp[mt][1] = 0.f; }
        #pragma unroll
        for (int mt = 0; mt < 2; mt++) {
            int rowA = 32 * mg + 16 * mt + gidx;
            int rowB = rowA + 8;
            #pragma unroll
            for (int j = 0; j < 5; j++) {
                int col0 = 8 * (5 * ng + j) + 2 * tig;
                float w0 = sW2[col0], w1 = sW2[col0 + 1];
                float h;
                h = acc[mt][j][0] + ((col0     < ADDP) ? sAdd[rowA * ADDP + col0]     : 0.f);
                rp[mt][0] += fmaxf(h, 0.f) * w0;
                h = acc[mt][j][1] + ((col0 + 1 < ADDP) ? sAdd[rowA * ADDP + col0 + 1] : 0.f);
                rp[mt][0] += fmaxf(h, 0.f) * w1;
                h = acc[mt][j][2] + ((col0     < ADDP) ? sAdd[rowB * ADDP + col0]     : 0.f);
                rp[mt][1] += fmaxf(h, 0.f) * w0;
                h = acc[mt][j][3] + ((col0 + 1 < ADDP) ? sAdd[rowB * ADDP + col0 + 1] : 0.f);
                rp[mt][1] += fmaxf(h, 0.f) * w1;
            }
        }
        #pragma unroll
        for (int off = 1; off <= 2; off <<= 1)
            #pragma unroll
            for (int mt = 0; mt < 2; mt++) {
                rp[mt][0] += __shfl_xor_sync(0xffffffffu, rp[mt][0], off);
                rp[mt][1] += __shfl_xor_sync(0xffffffffu, rp[mt][1], off);
            }
        if (tig == 0) {
            #pragma unroll
            for (int mt = 0; mt < 2; mt++) {
                int rowA = 32 * mg + 16 * mt + gidx;
                sPt[rowA * 4 + ng]       = rp[mt][0];
                sPt[(rowA + 8) * 4 + ng] = rp[mt][1];
            }
        }
    }
    __syncthreads();
    if (t < 128)
        sSc[t] = sPt[t * 4 + 0] + sPt[t * 4 + 1] + sPt[t * 4 + 2] + sPt[t * 4 + 3] + sMS[t];
    __syncthreads();

    // ---- fused per-span softmax (2 spans per CTA) ----
    if (w < 2) {
        int s = blockIdx.x * 2 + w;
        int cnt = ant_counts[s];
        float v0 = sSc[w * 64 + lane], v1 = sSc[w * 64 + lane + 32];
        bool val0 = lane < cnt, val1 = (lane + 32) < cnt;
        float mx = 0.f;  // epsilon logit = 0
        if (val0) mx = fmaxf(mx, v0);
        if (val1) mx = fmaxf(mx, v1);
        #pragma unroll
        for (int off = 16; off >= 1; off >>= 1)
            mx = fmaxf(mx, __shfl_xor_sync(0xffffffffu, mx, off));
        float e0 = val0 ? expf(v0 - mx) : 0.f;
        float e1 = val1 ? expf(v1 - mx) : 0.f;
        float sum = e0 + e1;
        #pragma unroll
        for (int off = 16; off >= 1; off >>= 1)
            sum += __shfl_xor_sync(0xffffffffu, sum, off);
        float eps = expf(-mx);
        sum += eps;
        float inv = 1.0f / sum;
        float* orow = out + (size_t)s * (K_ANT + 1);
        orow[lane]      = val0 ? e0 * inv : 1000.0f;
        orow[lane + 32] = val1 ? e1 * inv : 1000.0f;
        if (lane == 0) orow[K_ANT] = eps * inv;
    }
}

extern "C" void kernel_launch(void* const* d_in, const int* in_sizes, int n_in,
                              void* d_out, int out_size) {
    const float* g_i            = (const float*)d_in[0];
    const float* mention_scores = (const float*)d_in[1];
    const float* dist_embed     = (const float*)d_in[2];
    const float* genre_embed    = (const float*)d_in[3];
    const float* speaker_embed  = (const float*)d_in[4];
    const float* W1             = (const float*)d_in[5];
    const float* b1             = (const float*)d_in[6];
    const float* W2             = (const float*)d_in[7];
    const float* b2             = (const float*)d_in[8];
    const int*   mention_ids    = (const int*)d_in[9];
    const int*   antecedent_ids = (const int*)d_in[10];
    const int*   distances      = (const int*)d_in[11];
    const int*   genres         = (const int*)d_in[12];
    const int*   speakers       = (const int*)d_in[13];
    const int*   ant_counts     = (const int*)d_in[14];
    float* out = (float*)d_out;

    cudaFuncSetAttribute(main_kernel, cudaFuncAttributeMaxDynamicSharedMemorySize, SMEM_TOTAL);

    tables_kernel<<<(20 * H_DIM + 255) / 256, 256>>>(dist_embed, genre_embed,
                                                     speaker_embed, W1, b1);
    packw_kernel<<<(G_DIM * NPAD + 255) / 256, 256>>>(W1);
    ab_kernel<<<N_MENT / AB_ROWS, 160>>>(g_i, W1);
    main_kernel<<<S_SPANS / 2, 512, SMEM_TOTAL>>>(g_i, mention_scores, W2, b2,
                                                  mention_ids, antecedent_ids, distances,
                                                  genres, speakers, ant_counts, out);
}